// round 11
// baseline (speedup 1.0000x reference)
#include <cuda_runtime.h>

// Round 11: R9 champion (decoupled L1/L2 groups, named barriers, 4-deep
// handoff ring, original R5 tail) with three micro-cuts on the L1 pacer:
//  - WAIT_GE(flag2) hoisted from the store path to the top of L1BODY
//  - unclamped tanh for the g-gate (pre-activation provably < overflow
//    threshold); c-tanh keeps its clamp
//  - tail otherwise byte-identical to the 1048us champion

#define T_STEPS 1000

__device__ __forceinline__ float sigf(float x) {
    float e = exp2f(-1.4426950408889634f * x);
    return __fdividef(1.0f, 1.0f + e);
}
__device__ __forceinline__ float tanh_fast(float x) {      // clamped (for c)
    x = fminf(16.0f, fmaxf(-16.0f, x));
    float e = exp2f(-2.8853900817779268f * x);   // exp(-2x)
    return __fdividef(1.0f - e, 1.0f + e);
}
__device__ __forceinline__ float tanh_nc(float x) {        // unclamped (gate)
    float e = exp2f(-2.8853900817779268f * x);
    return __fdividef(1.0f - e, 1.0f + e);
}
__device__ __forceinline__ double pk2(float lo, float hi) {
    double r; asm("mov.b64 %0, {%1,%2};" : "=d"(r) : "f"(lo), "f"(hi)); return r;
}
__device__ __forceinline__ void upk2(double v, float &lo, float &hi) {
    asm("mov.b64 {%0,%1}, %2;" : "=f"(lo), "=f"(hi) : "d"(v));
}
__device__ __forceinline__ void fma2(double &acc, double a, double b) {
    asm("fma.rn.f32x2 %0, %1, %2, %0;" : "+d"(acc) : "d"(a), "d"(b));
}
__device__ __forceinline__ float fold(double v) {
    float lo, hi; upk2(v, lo, hi); return lo + hi;
}
__device__ __forceinline__ int ld_acq(const int* p) {
    int v;
    unsigned a = (unsigned)__cvta_generic_to_shared(p);
    asm volatile("ld.acquire.cta.shared.b32 %0, [%1];" : "=r"(v) : "r"(a) : "memory");
    return v;
}
__device__ __forceinline__ void st_rel(int* p, int v) {
    unsigned a = (unsigned)__cvta_generic_to_shared(p);
    asm volatile("st.release.cta.shared.b32 [%0], %1;" :: "r"(a), "r"(v) : "memory");
}
#define WAIT_GE(fp, tgt) while (ld_acq(fp) < (tgt)) { }

__global__ void __launch_bounds__(384, 1)
audio_lstm_kernel(const float* __restrict__ x,
                  const float* __restrict__ w_ih1, const float* __restrict__ w_hh1,
                  const float* __restrict__ b_ih1, const float* __restrict__ b_hh1,
                  const float* __restrict__ w_ih2, const float* __restrict__ w_hh2,
                  const float* __restrict__ b_ih2, const float* __restrict__ b_hh2,
                  const float* __restrict__ w_fc1, const float* __restrict__ b_fc1,
                  const float* __restrict__ w_fc2, const float* __restrict__ b_fc2,
                  float* __restrict__ out)
{
    // h1 pair rows (L1-internal), double buffered
    __shared__ __align__(16) float v1h[2][32][8];
    // x pair rows 0..12 + pad row 13 (L1-internal), double buffered
    __shared__ __align__(16) float xbuf[2][14][8];
    // handoff ring: pairs 0..31 = h1 (written by L1), 32..47 = h2 (L2-internal)
    __shared__ __align__(16) float v2s[4][48][8];
    __shared__ float sf[4][16];
    __shared__ int flag1, flag2;

    const int tid = threadIdx.x;
    const int bbase = blockIdx.x * 4;
    const bool isL1 = tid < 256;

    // Role-shared registers
    double whA[16], whB[16];     // L1: h-part weights / L2: first 16 pairs
    double wxA[8], wxB[8];       // L1: x-part weights / L2: last 8 pairs
    float bi, bf, bg, bo;
    float c = 0.0f;
    int u, sel, kh;

    if (isL1) {
        u = tid >> 2; sel = (tid >> 1) & 1; kh = tid & 1;
        const int gA = sel ? (128 + u) : u;          // g : i
        const int gB = sel ? (192 + u) : (64 + u);   // o : f
#pragma unroll
        for (int j = 0; j < 7; j++) {                // x pairs: p = 2j+kh < 13
            int p = 2 * j + kh;
            float a0 = 0.f, a1 = 0.f, q0 = 0.f, q1 = 0.f;
            if (p < 13) {
                int k0 = 2 * p, k1 = 2 * p + 1;
                a0 = w_ih1[gA * 26 + k0]; a1 = w_ih1[gA * 26 + k1];
                q0 = w_ih1[gB * 26 + k0]; q1 = w_ih1[gB * 26 + k1];
            }
            wxA[j] = pk2(a0, a1); wxB[j] = pk2(q0, q1);
        }
        wxA[7] = 0.0; wxB[7] = 0.0;
#pragma unroll
        for (int j = 0; j < 16; j++) {               // h pairs: p = 2j+kh < 32
            int p = 2 * j + kh;
            int k0 = 2 * p, k1 = 2 * p + 1;          // h index 0..63
            whA[j] = pk2(w_hh1[gA * 64 + k0], w_hh1[gA * 64 + k1]);
            whB[j] = pk2(w_hh1[gB * 64 + k0], w_hh1[gB * 64 + k1]);
        }
        bi = b_ih1[u] + b_hh1[u];
        bf = b_ih1[64 + u] + b_hh1[64 + u];
        bg = b_ih1[128 + u] + b_hh1[128 + u];
        bo = b_ih1[192 + u] + b_hh1[192 + u];
    } else {
        const int t2 = tid - 256;
        u = t2 >> 2; sel = (t2 >> 1) & 1; kh = t2 & 1;
        const int gA = sel ? (64 + u) : u;
        const int gB = sel ? (96 + u) : (32 + u);
#pragma unroll
        for (int kk = 0; kk < 24; kk++) {
            int p = kh * 24 + kk;
            int k0 = 2 * p, k1 = 2 * p + 1;
            float a0 = (k0 < 64) ? w_ih2[gA * 64 + k0] : w_hh2[gA * 32 + k0 - 64];
            float a1 = (k1 < 64) ? w_ih2[gA * 64 + k1] : w_hh2[gA * 32 + k1 - 64];
            float q0 = (k0 < 64) ? w_ih2[gB * 64 + k0] : w_hh2[gB * 32 + k0 - 64];
            float q1 = (k1 < 64) ? w_ih2[gB * 64 + k1] : w_hh2[gB * 32 + k1 - 64];
            if (kk < 16) { whA[kk] = pk2(a0, a1); whB[kk] = pk2(q0, q1); }
            else         { wxA[kk - 16] = pk2(a0, a1); wxB[kk - 16] = pk2(q0, q1); }
        }
        bi = b_ih2[u] + b_hh2[u];
        bf = b_ih2[32 + u] + b_hh2[32 + u];
        bg = b_ih2[64 + u] + b_hh2[64 + u];
        bo = b_ih2[96 + u] + b_hh2[96 + u];
    }

    const int hrow = u >> 1;
    const int hlane = u & 1;
    const int myb = 2 * kh + sel;

    // Zero buffers + init flags
    for (int idx = tid; idx < 2 * 32 * 8; idx += 384) ((float*)v1h)[idx] = 0.0f;
    for (int idx = tid; idx < 2 * 14 * 8; idx += 384) ((float*)xbuf)[idx] = 0.0f;
    for (int idx = tid; idx < 4 * 48 * 8; idx += 384) ((float*)v2s)[idx] = 0.0f;
    if (tid == 0) { flag1 = -1; flag2 = 0; }

    // x layout: x[b][i][t]  (loaders are L1 threads)
    const int xi = tid % 26;
    const int xb = tid / 26;
    const bool isldr = tid < 104;
    const int xrow = xi >> 1, xcol = xb * 2 + (xi & 1);
    const float* xptr = x + (size_t)(bbase + xb) * 26 * T_STEPS + (size_t)xi * T_STEPS;
    __syncthreads();
    if (isldr) {
        xbuf[0][xrow][xcol] = xptr[0];
        xbuf[1][xrow][xcol] = xptr[1];
    }
    __syncthreads();

    // carried x-part accumulators
    double xA0 = 0, xA1 = 0, xA2 = 0, xA3 = 0, xB0 = 0, xB1 = 0, xB2 = 0, xB3 = 0;
    if (isL1) {   // precompute x-part for step 0 from xbuf[0]
#pragma unroll
        for (int j = 0; j < 7; j++) {
            const float* r = &xbuf[0][2 * j + kh][0];
            double2 vlo = *(const double2*)r;
            double2 vhi = *(const double2*)(r + 4);
            fma2(xA0, wxA[j], vlo.x); fma2(xA1, wxA[j], vlo.y);
            fma2(xA2, wxA[j], vhi.x); fma2(xA3, wxA[j], vhi.y);
            fma2(xB0, wxB[j], vlo.x); fma2(xB1, wxB[j], vlo.y);
            fma2(xB2, wxB[j], vhi.x); fma2(xB3, wxB[j], vhi.y);
        }
    }

    // L1 body at iter n: reads v1h[cur] + carried xacc; writes v1h[nxt],
    // v2s[vb] rows 0..31 (vb = n&3); stages x[n+2]; precomputes xacc for n+1.
    // WAIT on flag2 hoisted to the TOP (off the store->barrier chain).
#define L1BODY(n, cur, nxt, vb)                                                    \
    {                                                                              \
        WAIT_GE(&flag2, (n) - 3);   /* ring slot vb free? (3-step slack) */        \
        float xr = 0.0f;                                                           \
        const bool ldr = isldr && ((n) + 2 < T_STEPS);                             \
        if (ldr) xr = xptr[(n) + 2];                                               \
        double aA0 = xA0, aA1 = xA1, aA2 = xA2, aA3 = xA3;                         \
        double aB0 = xB0, aB1 = xB1, aB2 = xB2, aB3 = xB3;                         \
        _Pragma("unroll")                                                          \
        for (int j = 0; j < 16; j++) {                                             \
            const float* r = &v1h[cur][2 * j + kh][0];                             \
            double2 vlo = *(const double2*)r;                                      \
            double2 vhi = *(const double2*)(r + 4);                                \
            fma2(aA0, whA[j], vlo.x); fma2(aA1, whA[j], vlo.y);                    \
            fma2(aA2, whA[j], vhi.x); fma2(aA3, whA[j], vhi.y);                    \
            fma2(aB0, whB[j], vlo.x); fma2(aB1, whB[j], vlo.y);                    \
            fma2(aB2, whB[j], vhi.x); fma2(aB3, whB[j], vhi.y);                    \
        }                                                                          \
        float pA0 = fold(aA0), pA1 = fold(aA1), pA2 = fold(aA2), pA3 = fold(aA3);  \
        float pB0 = fold(aB0), pB1 = fold(aB1), pB2 = fold(aB2), pB3 = fold(aB3);  \
        float sA0 = kh ? pA0 : pA2, sA1 = kh ? pA1 : pA3;                          \
        float sB0 = kh ? pB0 : pB2, sB1 = kh ? pB1 : pB3;                          \
        sA0 = __shfl_xor_sync(0xffffffffu, sA0, 1);                                \
        sA1 = __shfl_xor_sync(0xffffffffu, sA1, 1);                                \
        sB0 = __shfl_xor_sync(0xffffffffu, sB0, 1);                                \
        sB1 = __shfl_xor_sync(0xffffffffu, sB1, 1);                                \
        float mA0 = (kh ? pA2 : pA0) + sA0;                                        \
        float mA1 = (kh ? pA3 : pA1) + sA1;                                        \
        float mB0 = (kh ? pB2 : pB0) + sB0;                                        \
        float mB1 = (kh ? pB3 : pB1) + sB1;                                        \
        float rA = __shfl_xor_sync(0xffffffffu, sel ? mA0 : mA1, 2);               \
        float rB = __shfl_xor_sync(0xffffffffu, sel ? mB0 : mB1, 2);               \
        float ownA = sel ? mA1 : mA0, ownB = sel ? mB1 : mB0;                      \
        float gi = (sel ? rA : ownA) + bi;                                         \
        float gf = (sel ? rB : ownB) + bf;                                         \
        float gg = (sel ? ownA : rA) + bg;                                         \
        float go = (sel ? ownB : rB) + bo;                                         \
        gi = sigf(gi); gf = sigf(gf); gg = tanh_nc(gg); go = sigf(go);             \
        c = fmaf(gf, c, gi * gg);                                                  \
        float h = go * tanh_fast(c);                                               \
        v1h[nxt][hrow][myb * 2 + hlane] = h;                                       \
        v2s[vb][hrow][myb * 2 + hlane] = h;                                        \
        if (ldr) xbuf[cur][xrow][xcol] = xr;                                       \
        if ((n) + 1 < T_STEPS) {                                                   \
            xA0 = 0; xA1 = 0; xA2 = 0; xA3 = 0;                                    \
            xB0 = 0; xB1 = 0; xB2 = 0; xB3 = 0;                                    \
            _Pragma("unroll")                                                      \
            for (int j = 0; j < 7; j++) {                                          \
                const float* r = &xbuf[nxt][2 * j + kh][0];                        \
                double2 vlo = *(const double2*)r;                                  \
                double2 vhi = *(const double2*)(r + 4);                            \
                fma2(xA0, wxA[j], vlo.x); fma2(xA1, wxA[j], vlo.y);                \
                fma2(xA2, wxA[j], vhi.x); fma2(xA3, wxA[j], vhi.y);                \
                fma2(xB0, wxB[j], vlo.x); fma2(xB1, wxB[j], vlo.y);                \
                fma2(xB2, wxB[j], vhi.x); fma2(xB3, wxB[j], vhi.y);                \
            }                                                                      \
        }                                                                          \
        asm volatile("bar.sync 1, 256;" ::: "memory");                             \
        if (tid == 0) st_rel(&flag1, (n));                                         \
    }

    // L2 body at iter n (computes LSTM-2 step n-1): reads v2s[rd] (rd=(n-1)&3),
    // writes h2 into v2s[wr] rows 32..47 (wr=n&3).
#define L2BODY(n, rd, wr)                                                          \
    {                                                                              \
        WAIT_GE(&flag1, (n) - 1);   /* h1 of step n-1 published? */                \
        double aA0 = 0, aA1 = 0, aA2 = 0, aA3 = 0;                                 \
        double aB0 = 0, aB1 = 0, aB2 = 0, aB3 = 0;                                 \
        const float* base = &v2s[rd][kh * 24][0];                                  \
        _Pragma("unroll")                                                          \
        for (int kk = 0; kk < 24; kk++) {                                          \
            const float* r = base + 8 * kk;                                        \
            double2 vlo = *(const double2*)r;                                      \
            double2 vhi = *(const double2*)(r + 4);                                \
            double wa = (kk < 16) ? whA[kk] : wxA[kk - 16];                        \
            double wb = (kk < 16) ? whB[kk] : wxB[kk - 16];                        \
            fma2(aA0, wa, vlo.x); fma2(aA1, wa, vlo.y);                            \
            fma2(aA2, wa, vhi.x); fma2(aA3, wa, vhi.y);                            \
            fma2(aB0, wb, vlo.x); fma2(aB1, wb, vlo.y);                            \
            fma2(aB2, wb, vhi.x); fma2(aB3, wb, vhi.y);                            \
        }                                                                          \
        float pA0 = fold(aA0), pA1 = fold(aA1), pA2 = fold(aA2), pA3 = fold(aA3);  \
        float pB0 = fold(aB0), pB1 = fold(aB1), pB2 = fold(aB2), pB3 = fold(aB3);  \
        float sA0 = kh ? pA0 : pA2, sA1 = kh ? pA1 : pA3;                          \
        float sB0 = kh ? pB0 : pB2, sB1 = kh ? pB1 : pB3;                          \
        sA0 = __shfl_xor_sync(0xffffffffu, sA0, 1);                                \
        sA1 = __shfl_xor_sync(0xffffffffu, sA1, 1);                                \
        sB0 = __shfl_xor_sync(0xffffffffu, sB0, 1);                                \
        sB1 = __shfl_xor_sync(0xffffffffu, sB1, 1);                                \
        float mA0 = (kh ? pA2 : pA0) + sA0;                                        \
        float mA1 = (kh ? pA3 : pA1) + sA1;                                        \
        float mB0 = (kh ? pB2 : pB0) + sB0;                                        \
        float mB1 = (kh ? pB3 : pB1) + sB1;                                        \
        float rA = __shfl_xor_sync(0xffffffffu, sel ? mA0 : mA1, 2);               \
        float rB = __shfl_xor_sync(0xffffffffu, sel ? mB0 : mB1, 2);               \
        float ownA = sel ? mA1 : mA0, ownB = sel ? mB1 : mB0;                      \
        float gi = (sel ? rA : ownA) + bi;                                         \
        float gf = (sel ? rB : ownB) + bf;                                         \
        float gg = (sel ? ownA : rA) + bg;                                         \
        float go = (sel ? ownB : rB) + bo;                                         \
        gi = sigf(gi); gf = sigf(gf); gg = tanh_nc(gg); go = sigf(go);             \
        c = fmaf(gf, c, gi * gg);                                                  \
        float h = go * tanh_fast(c);                                               \
        v2s[wr][32 + hrow][myb * 2 + hlane] = h;                                   \
        asm volatile("bar.sync 2, 128;" ::: "memory");                             \
        if (tid == 256) st_rel(&flag2, (n));                                       \
    }

    if (isL1) {
        for (int n = 0; n < T_STEPS; n += 4) {
            L1BODY(n,     0, 1, 0);
            L1BODY(n + 1, 1, 0, 1);
            L1BODY(n + 2, 0, 1, 2);
            L1BODY(n + 3, 1, 0, 3);
        }
    } else {
        for (int n = 1; n <= T_STEPS; n += 4) {
            L2BODY(n,     0, 1);
            L2BODY(n + 1, 1, 2);
            L2BODY(n + 2, 2, 3);
            L2BODY(n + 3, 3, 0);
        }
    }
#undef L1BODY
#undef L2BODY
    __syncthreads();

    // ================= MLP head =================
    // final h2 (step 999, L2 iter 1000) is in v2s[0] pairs 32..47
    if (tid < 64) {
        const int b = tid >> 4, j = tid & 15;
        float s = b_fc1[j];
#pragma unroll
        for (int k2 = 0; k2 < 32; k2++)
            s = fmaf(v2s[0][32 + (k2 >> 1)][b * 2 + (k2 & 1)], w_fc1[j * 32 + k2], s);
        sf[b][j] = fmaxf(s, 0.0f);
    }
    __syncthreads();
    if (tid < 40) {
        const int b = tid / 10, o = tid % 10;
        float s = b_fc2[o];
#pragma unroll
        for (int j = 0; j < 16; j++) s = fmaf(sf[b][j], w_fc2[o * 16 + j], s);
        out[(bbase + b) * 10 + o] = s;
    }
}

extern "C" void kernel_launch(void* const* d_in, const int* in_sizes, int n_in,
                              void* d_out, int out_size)
{
    const float* x     = (const float*)d_in[0];
    const float* w_ih1 = (const float*)d_in[1];
    const float* w_hh1 = (const float*)d_in[2];
    const float* b_ih1 = (const float*)d_in[3];
    const float* b_hh1 = (const float*)d_in[4];
    const float* w_ih2 = (const float*)d_in[5];
    const float* w_hh2 = (const float*)d_in[6];
    const float* b_ih2 = (const float*)d_in[7];
    const float* b_hh2 = (const float*)d_in[8];
    const float* w_fc1 = (const float*)d_in[9];
    const float* b_fc1 = (const float*)d_in[10];
    const float* w_fc2 = (const float*)d_in[11];
    const float* b_fc2 = (const float*)d_in[12];
    float* out = (float*)d_out;

    audio_lstm_kernel<<<128, 384>>>(x, w_ih1, w_hh1, b_ih1, b_hh1,
                                    w_ih2, w_hh2, b_ih2, b_hh2,
                                    w_fc1, b_fc1, w_fc2, b_fc2, out);
}

// round 12
// speedup vs baseline: 1.1145x; 1.1145x over previous
#include <cuda_runtime.h>

// Round 12: R9 champion (decoupled L1/L2 groups, named barriers, 4-deep
// handoff ring) byte-identical EXCEPT activations use hardware
// tanh.approx.f32 (single fast MUFU op):
//   tanh(x)    = tanh.approx(x)
//   sigmoid(x) = 0.5*tanh.approx(0.5x) + 0.5
// (retest of the R6 change, whose regression is attributed to a DVFS
// artifact: fma busy-cycles cannot rise when FLOPs are removed).

#define T_STEPS 1000

__device__ __forceinline__ float tanhf_a(float x) {
    float r; asm("tanh.approx.f32 %0, %1;" : "=f"(r) : "f"(x)); return r;
}
__device__ __forceinline__ float sigf(float x) {
    return fmaf(0.5f, tanhf_a(0.5f * x), 0.5f);
}
__device__ __forceinline__ float tanh_fast(float x) {
    return tanhf_a(x);
}
__device__ __forceinline__ double pk2(float lo, float hi) {
    double r; asm("mov.b64 %0, {%1,%2};" : "=d"(r) : "f"(lo), "f"(hi)); return r;
}
__device__ __forceinline__ void upk2(double v, float &lo, float &hi) {
    asm("mov.b64 {%0,%1}, %2;" : "=f"(lo), "=f"(hi) : "d"(v));
}
__device__ __forceinline__ void fma2(double &acc, double a, double b) {
    asm("fma.rn.f32x2 %0, %1, %2, %0;" : "+d"(acc) : "d"(a), "d"(b));
}
__device__ __forceinline__ float fold(double v) {
    float lo, hi; upk2(v, lo, hi); return lo + hi;
}
__device__ __forceinline__ int ld_acq(const int* p) {
    int v;
    unsigned a = (unsigned)__cvta_generic_to_shared(p);
    asm volatile("ld.acquire.cta.shared.b32 %0, [%1];" : "=r"(v) : "r"(a) : "memory");
    return v;
}
__device__ __forceinline__ void st_rel(int* p, int v) {
    unsigned a = (unsigned)__cvta_generic_to_shared(p);
    asm volatile("st.release.cta.shared.b32 [%0], %1;" :: "r"(a), "r"(v) : "memory");
}
#define WAIT_GE(fp, tgt) while (ld_acq(fp) < (tgt)) { }

__global__ void __launch_bounds__(384, 1)
audio_lstm_kernel(const float* __restrict__ x,
                  const float* __restrict__ w_ih1, const float* __restrict__ w_hh1,
                  const float* __restrict__ b_ih1, const float* __restrict__ b_hh1,
                  const float* __restrict__ w_ih2, const float* __restrict__ w_hh2,
                  const float* __restrict__ b_ih2, const float* __restrict__ b_hh2,
                  const float* __restrict__ w_fc1, const float* __restrict__ b_fc1,
                  const float* __restrict__ w_fc2, const float* __restrict__ b_fc2,
                  float* __restrict__ out)
{
    // h1 pair rows (L1-internal), double buffered
    __shared__ __align__(16) float v1h[2][32][8];
    // x pair rows 0..12 + pad row 13 (L1-internal), double buffered
    __shared__ __align__(16) float xbuf[2][14][8];
    // handoff ring: pairs 0..31 = h1 (written by L1), 32..47 = h2 (L2-internal)
    __shared__ __align__(16) float v2s[4][48][8];
    __shared__ float sf[4][16];
    __shared__ int flag1, flag2;

    const int tid = threadIdx.x;
    const int bbase = blockIdx.x * 4;
    const bool isL1 = tid < 256;

    // Role-shared registers
    double whA[16], whB[16];     // L1: h-part weights / L2: first 16 pairs
    double wxA[8], wxB[8];       // L1: x-part weights / L2: last 8 pairs
    float bi, bf, bg, bo;
    float c = 0.0f;
    int u, sel, kh;

    if (isL1) {
        u = tid >> 2; sel = (tid >> 1) & 1; kh = tid & 1;
        const int gA = sel ? (128 + u) : u;          // g : i
        const int gB = sel ? (192 + u) : (64 + u);   // o : f
#pragma unroll
        for (int j = 0; j < 7; j++) {                // x pairs: p = 2j+kh < 13
            int p = 2 * j + kh;
            float a0 = 0.f, a1 = 0.f, q0 = 0.f, q1 = 0.f;
            if (p < 13) {
                int k0 = 2 * p, k1 = 2 * p + 1;
                a0 = w_ih1[gA * 26 + k0]; a1 = w_ih1[gA * 26 + k1];
                q0 = w_ih1[gB * 26 + k0]; q1 = w_ih1[gB * 26 + k1];
            }
            wxA[j] = pk2(a0, a1); wxB[j] = pk2(q0, q1);
        }
        wxA[7] = 0.0; wxB[7] = 0.0;
#pragma unroll
        for (int j = 0; j < 16; j++) {               // h pairs: p = 2j+kh < 32
            int p = 2 * j + kh;
            int k0 = 2 * p, k1 = 2 * p + 1;          // h index 0..63
            whA[j] = pk2(w_hh1[gA * 64 + k0], w_hh1[gA * 64 + k1]);
            whB[j] = pk2(w_hh1[gB * 64 + k0], w_hh1[gB * 64 + k1]);
        }
        bi = b_ih1[u] + b_hh1[u];
        bf = b_ih1[64 + u] + b_hh1[64 + u];
        bg = b_ih1[128 + u] + b_hh1[128 + u];
        bo = b_ih1[192 + u] + b_hh1[192 + u];
    } else {
        const int t2 = tid - 256;
        u = t2 >> 2; sel = (t2 >> 1) & 1; kh = t2 & 1;
        const int gA = sel ? (64 + u) : u;
        const int gB = sel ? (96 + u) : (32 + u);
#pragma unroll
        for (int kk = 0; kk < 24; kk++) {
            int p = kh * 24 + kk;
            int k0 = 2 * p, k1 = 2 * p + 1;
            float a0 = (k0 < 64) ? w_ih2[gA * 64 + k0] : w_hh2[gA * 32 + k0 - 64];
            float a1 = (k1 < 64) ? w_ih2[gA * 64 + k1] : w_hh2[gA * 32 + k1 - 64];
            float q0 = (k0 < 64) ? w_ih2[gB * 64 + k0] : w_hh2[gB * 32 + k0 - 64];
            float q1 = (k1 < 64) ? w_ih2[gB * 64 + k1] : w_hh2[gB * 32 + k1 - 64];
            if (kk < 16) { whA[kk] = pk2(a0, a1); whB[kk] = pk2(q0, q1); }
            else         { wxA[kk - 16] = pk2(a0, a1); wxB[kk - 16] = pk2(q0, q1); }
        }
        bi = b_ih2[u] + b_hh2[u];
        bf = b_ih2[32 + u] + b_hh2[32 + u];
        bg = b_ih2[64 + u] + b_hh2[64 + u];
        bo = b_ih2[96 + u] + b_hh2[96 + u];
    }

    const int hrow = u >> 1;
    const int hlane = u & 1;
    const int myb = 2 * kh + sel;

    // Zero buffers + init flags
    for (int idx = tid; idx < 2 * 32 * 8; idx += 384) ((float*)v1h)[idx] = 0.0f;
    for (int idx = tid; idx < 2 * 14 * 8; idx += 384) ((float*)xbuf)[idx] = 0.0f;
    for (int idx = tid; idx < 4 * 48 * 8; idx += 384) ((float*)v2s)[idx] = 0.0f;
    if (tid == 0) { flag1 = -1; flag2 = 0; }

    // x layout: x[b][i][t]  (loaders are L1 threads)
    const int xi = tid % 26;
    const int xb = tid / 26;
    const bool isldr = tid < 104;
    const int xrow = xi >> 1, xcol = xb * 2 + (xi & 1);
    const float* xptr = x + (size_t)(bbase + xb) * 26 * T_STEPS + (size_t)xi * T_STEPS;
    __syncthreads();
    if (isldr) {
        xbuf[0][xrow][xcol] = xptr[0];
        xbuf[1][xrow][xcol] = xptr[1];
    }
    __syncthreads();

    // carried x-part accumulators
    double xA0 = 0, xA1 = 0, xA2 = 0, xA3 = 0, xB0 = 0, xB1 = 0, xB2 = 0, xB3 = 0;
    if (isL1) {   // precompute x-part for step 0 from xbuf[0]
#pragma unroll
        for (int j = 0; j < 7; j++) {
            const float* r = &xbuf[0][2 * j + kh][0];
            double2 vlo = *(const double2*)r;
            double2 vhi = *(const double2*)(r + 4);
            fma2(xA0, wxA[j], vlo.x); fma2(xA1, wxA[j], vlo.y);
            fma2(xA2, wxA[j], vhi.x); fma2(xA3, wxA[j], vhi.y);
            fma2(xB0, wxB[j], vlo.x); fma2(xB1, wxB[j], vlo.y);
            fma2(xB2, wxB[j], vhi.x); fma2(xB3, wxB[j], vhi.y);
        }
    }

    // L1 body at iter n: reads v1h[cur] + carried xacc; writes v1h[nxt],
    // v2s[vb] rows 0..31 (vb = n&3); stages x[n+2]; precomputes xacc for n+1.
#define L1BODY(n, cur, nxt, vb)                                                    \
    {                                                                              \
        float xr = 0.0f;                                                           \
        const bool ldr = isldr && ((n) + 2 < T_STEPS);                             \
        if (ldr) xr = xptr[(n) + 2];                                               \
        double aA0 = xA0, aA1 = xA1, aA2 = xA2, aA3 = xA3;                         \
        double aB0 = xB0, aB1 = xB1, aB2 = xB2, aB3 = xB3;                         \
        _Pragma("unroll")                                                          \
        for (int j = 0; j < 16; j++) {                                             \
            const float* r = &v1h[cur][2 * j + kh][0];                             \
            double2 vlo = *(const double2*)r;                                      \
            double2 vhi = *(const double2*)(r + 4);                                \
            fma2(aA0, whA[j], vlo.x); fma2(aA1, whA[j], vlo.y);                    \
            fma2(aA2, whA[j], vhi.x); fma2(aA3, whA[j], vhi.y);                    \
            fma2(aB0, whB[j], vlo.x); fma2(aB1, whB[j], vlo.y);                    \
            fma2(aB2, whB[j], vhi.x); fma2(aB3, whB[j], vhi.y);                    \
        }                                                                          \
        float pA0 = fold(aA0), pA1 = fold(aA1), pA2 = fold(aA2), pA3 = fold(aA3);  \
        float pB0 = fold(aB0), pB1 = fold(aB1), pB2 = fold(aB2), pB3 = fold(aB3);  \
        float sA0 = kh ? pA0 : pA2, sA1 = kh ? pA1 : pA3;                          \
        float sB0 = kh ? pB0 : pB2, sB1 = kh ? pB1 : pB3;                          \
        sA0 = __shfl_xor_sync(0xffffffffu, sA0, 1);                                \
        sA1 = __shfl_xor_sync(0xffffffffu, sA1, 1);                                \
        sB0 = __shfl_xor_sync(0xffffffffu, sB0, 1);                                \
        sB1 = __shfl_xor_sync(0xffffffffu, sB1, 1);                                \
        float mA0 = (kh ? pA2 : pA0) + sA0;                                        \
        float mA1 = (kh ? pA3 : pA1) + sA1;                                        \
        float mB0 = (kh ? pB2 : pB0) + sB0;                                        \
        float mB1 = (kh ? pB3 : pB1) + sB1;                                        \
        float rA = __shfl_xor_sync(0xffffffffu, sel ? mA0 : mA1, 2);               \
        float rB = __shfl_xor_sync(0xffffffffu, sel ? mB0 : mB1, 2);               \
        float ownA = sel ? mA1 : mA0, ownB = sel ? mB1 : mB0;                      \
        float gi = (sel ? rA : ownA) + bi;                                         \
        float gf = (sel ? rB : ownB) + bf;                                         \
        float gg = (sel ? ownA : rA) + bg;                                         \
        float go = (sel ? ownB : rB) + bo;                                         \
        gi = sigf(gi); gf = sigf(gf); gg = tanh_fast(gg); go = sigf(go);           \
        c = fmaf(gf, c, gi * gg);                                                  \
        float h = go * tanh_fast(c);                                               \
        WAIT_GE(&flag2, (n) - 3);   /* ring slot vb free? (3-step slack) */        \
        v1h[nxt][hrow][myb * 2 + hlane] = h;                                       \
        v2s[vb][hrow][myb * 2 + hlane] = h;                                        \
        if (ldr) xbuf[cur][xrow][xcol] = xr;                                       \
        if ((n) + 1 < T_STEPS) {                                                   \
            xA0 = 0; xA1 = 0; xA2 = 0; xA3 = 0;                                    \
            xB0 = 0; xB1 = 0; xB2 = 0; xB3 = 0;                                    \
            _Pragma("unroll")                                                      \
            for (int j = 0; j < 7; j++) {                                          \
                const float* r = &xbuf[nxt][2 * j + kh][0];                        \
                double2 vlo = *(const double2*)r;                                  \
                double2 vhi = *(const double2*)(r + 4);                            \
                fma2(xA0, wxA[j], vlo.x); fma2(xA1, wxA[j], vlo.y);                \
                fma2(xA2, wxA[j], vhi.x); fma2(xA3, wxA[j], vhi.y);                \
                fma2(xB0, wxB[j], vlo.x); fma2(xB1, wxB[j], vlo.y);                \
                fma2(xB2, wxB[j], vhi.x); fma2(xB3, wxB[j], vhi.y);                \
            }                                                                      \
        }                                                                          \
        asm volatile("bar.sync 1, 256;" ::: "memory");                             \
        if (tid == 0) st_rel(&flag1, (n));                                         \
    }

    // L2 body at iter n (computes LSTM-2 step n-1): reads v2s[rd] (rd=(n-1)&3),
    // writes h2 into v2s[wr] rows 32..47 (wr=n&3).
#define L2BODY(n, rd, wr)                                                          \
    {                                                                              \
        WAIT_GE(&flag1, (n) - 1);   /* h1 of step n-1 published? */                \
        double aA0 = 0, aA1 = 0, aA2 = 0, aA3 = 0;                                 \
        double aB0 = 0, aB1 = 0, aB2 = 0, aB3 = 0;                                 \
        const float* base = &v2s[rd][kh * 24][0];                                  \
        _Pragma("unroll")                                                          \
        for (int kk = 0; kk < 24; kk++) {                                          \
            const float* r = base + 8 * kk;                                        \
            double2 vlo = *(const double2*)r;                                      \
            double2 vhi = *(const double2*)(r + 4);                                \
            double wa = (kk < 16) ? whA[kk] : wxA[kk - 16];                        \
            double wb = (kk < 16) ? whB[kk] : wxB[kk - 16];                        \
            fma2(aA0, wa, vlo.x); fma2(aA1, wa, vlo.y);                            \
            fma2(aA2, wa, vhi.x); fma2(aA3, wa, vhi.y);                            \
            fma2(aB0, wb, vlo.x); fma2(aB1, wb, vlo.y);                            \
            fma2(aB2, wb, vhi.x); fma2(aB3, wb, vhi.y);                            \
        }                                                                          \
        float pA0 = fold(aA0), pA1 = fold(aA1), pA2 = fold(aA2), pA3 = fold(aA3);  \
        float pB0 = fold(aB0), pB1 = fold(aB1), pB2 = fold(aB2), pB3 = fold(aB3);  \
        float sA0 = kh ? pA0 : pA2, sA1 = kh ? pA1 : pA3;                          \
        float sB0 = kh ? pB0 : pB2, sB1 = kh ? pB1 : pB3;                          \
        sA0 = __shfl_xor_sync(0xffffffffu, sA0, 1);                                \
        sA1 = __shfl_xor_sync(0xffffffffu, sA1, 1);                                \
        sB0 = __shfl_xor_sync(0xffffffffu, sB0, 1);                                \
        sB1 = __shfl_xor_sync(0xffffffffu, sB1, 1);                                \
        float mA0 = (kh ? pA2 : pA0) + sA0;                                        \
        float mA1 = (kh ? pA3 : pA1) + sA1;                                        \
        float mB0 = (kh ? pB2 : pB0) + sB0;                                        \
        float mB1 = (kh ? pB3 : pB1) + sB1;                                        \
        float rA = __shfl_xor_sync(0xffffffffu, sel ? mA0 : mA1, 2);               \
        float rB = __shfl_xor_sync(0xffffffffu, sel ? mB0 : mB1, 2);               \
        float ownA = sel ? mA1 : mA0, ownB = sel ? mB1 : mB0;                      \
        float gi = (sel ? rA : ownA) + bi;                                         \
        float gf = (sel ? rB : ownB) + bf;                                         \
        float gg = (sel ? ownA : rA) + bg;                                         \
        float go = (sel ? ownB : rB) + bo;                                         \
        gi = sigf(gi); gf = sigf(gf); gg = tanh_fast(gg); go = sigf(go);           \
        c = fmaf(gf, c, gi * gg);                                                  \
        float h = go * tanh_fast(c);                                               \
        v2s[wr][32 + hrow][myb * 2 + hlane] = h;                                   \
        asm volatile("bar.sync 2, 128;" ::: "memory");                             \
        if (tid == 256) st_rel(&flag2, (n));                                       \
    }

    if (isL1) {
        for (int n = 0; n < T_STEPS; n += 4) {
            L1BODY(n,     0, 1, 0);
            L1BODY(n + 1, 1, 0, 1);
            L1BODY(n + 2, 0, 1, 2);
            L1BODY(n + 3, 1, 0, 3);
        }
    } else {
        for (int n = 1; n <= T_STEPS; n += 4) {
            L2BODY(n,     0, 1);
            L2BODY(n + 1, 1, 2);
            L2BODY(n + 2, 2, 3);
            L2BODY(n + 3, 3, 0);
        }
    }
#undef L1BODY
#undef L2BODY
    __syncthreads();

    // ================= MLP head =================
    // final h2 (step 999, L2 iter 1000) is in v2s[0] pairs 32..47
    if (tid < 64) {
        const int b = tid >> 4, j = tid & 15;
        float s = b_fc1[j];
#pragma unroll
        for (int k2 = 0; k2 < 32; k2++)
            s = fmaf(v2s[0][32 + (k2 >> 1)][b * 2 + (k2 & 1)], w_fc1[j * 32 + k2], s);
        sf[b][j] = fmaxf(s, 0.0f);
    }
    __syncthreads();
    if (tid < 40) {
        const int b = tid / 10, o = tid % 10;
        float s = b_fc2[o];
#pragma unroll
        for (int j = 0; j < 16; j++) s = fmaf(sf[b][j], w_fc2[o * 16 + j], s);
        out[(bbase + b) * 10 + o] = s;
    }
}

extern "C" void kernel_launch(void* const* d_in, const int* in_sizes, int n_in,
                              void* d_out, int out_size)
{
    const float* x     = (const float*)d_in[0];
    const float* w_ih1 = (const float*)d_in[1];
    const float* w_hh1 = (const float*)d_in[2];
    const float* b_ih1 = (const float*)d_in[3];
    const float* b_hh1 = (const float*)d_in[4];
    const float* w_ih2 = (const float*)d_in[5];
    const float* w_hh2 = (const float*)d_in[6];
    const float* b_ih2 = (const float*)d_in[7];
    const float* b_hh2 = (const float*)d_in[8];
    const float* w_fc1 = (const float*)d_in[9];
    const float* b_fc1 = (const float*)d_in[10];
    const float* w_fc2 = (const float*)d_in[11];
    const float* b_fc2 = (const float*)d_in[12];
    float* out = (float*)d_out;

    audio_lstm_kernel<<<128, 384>>>(x, w_ih1, w_hh1, b_ih1, b_hh1,
                                    w_ih2, w_hh2, b_ih2, b_hh2,
                                    w_fc1, b_fc1, w_fc2, b_fc2, out);
}

// round 13
// speedup vs baseline: 1.1231x; 1.0077x over previous
#include <cuda_runtime.h>

// Round 13: R12 champion (decoupled groups + tanh.approx activations) with
// sigmoid PRE-SCALING folded into the weights:
//   weights/biases of sigmoid gates (i,f,o) are halved at load time, so
//   sigmoid(x) = 0.5*tanh.approx(x_prescaled) + 0.5  — no input FMUL.
//   (gate g / tanh weights stay unscaled.)
// Everything else byte-identical to the 981us champion.

#define T_STEPS 1000

__device__ __forceinline__ float tanhf_a(float x) {
    float r; asm("tanh.approx.f32 %0, %1;" : "=f"(r) : "f"(x)); return r;
}
// input already pre-scaled by 0.5 via weights/bias
__device__ __forceinline__ float sigf_h(float x) {
    return fmaf(0.5f, tanhf_a(x), 0.5f);
}
__device__ __forceinline__ float tanh_fast(float x) {
    return tanhf_a(x);
}
__device__ __forceinline__ double pk2(float lo, float hi) {
    double r; asm("mov.b64 %0, {%1,%2};" : "=d"(r) : "f"(lo), "f"(hi)); return r;
}
__device__ __forceinline__ void upk2(double v, float &lo, float &hi) {
    asm("mov.b64 {%0,%1}, %2;" : "=f"(lo), "=f"(hi) : "d"(v));
}
__device__ __forceinline__ void fma2(double &acc, double a, double b) {
    asm("fma.rn.f32x2 %0, %1, %2, %0;" : "+d"(acc) : "d"(a), "d"(b));
}
__device__ __forceinline__ float fold(double v) {
    float lo, hi; upk2(v, lo, hi); return lo + hi;
}
__device__ __forceinline__ int ld_acq(const int* p) {
    int v;
    unsigned a = (unsigned)__cvta_generic_to_shared(p);
    asm volatile("ld.acquire.cta.shared.b32 %0, [%1];" : "=r"(v) : "r"(a) : "memory");
    return v;
}
__device__ __forceinline__ void st_rel(int* p, int v) {
    unsigned a = (unsigned)__cvta_generic_to_shared(p);
    asm volatile("st.release.cta.shared.b32 [%0], %1;" :: "r"(a), "r"(v) : "memory");
}
#define WAIT_GE(fp, tgt) while (ld_acq(fp) < (tgt)) { }

__global__ void __launch_bounds__(384, 1)
audio_lstm_kernel(const float* __restrict__ x,
                  const float* __restrict__ w_ih1, const float* __restrict__ w_hh1,
                  const float* __restrict__ b_ih1, const float* __restrict__ b_hh1,
                  const float* __restrict__ w_ih2, const float* __restrict__ w_hh2,
                  const float* __restrict__ b_ih2, const float* __restrict__ b_hh2,
                  const float* __restrict__ w_fc1, const float* __restrict__ b_fc1,
                  const float* __restrict__ w_fc2, const float* __restrict__ b_fc2,
                  float* __restrict__ out)
{
    // h1 pair rows (L1-internal), double buffered
    __shared__ __align__(16) float v1h[2][32][8];
    // x pair rows 0..12 + pad row 13 (L1-internal), double buffered
    __shared__ __align__(16) float xbuf[2][14][8];
    // handoff ring: pairs 0..31 = h1 (written by L1), 32..47 = h2 (L2-internal)
    __shared__ __align__(16) float v2s[4][48][8];
    __shared__ float sf[4][16];
    __shared__ int flag1, flag2;

    const int tid = threadIdx.x;
    const int bbase = blockIdx.x * 4;
    const bool isL1 = tid < 256;

    // Role-shared registers
    double whA[16], whB[16];     // L1: h-part weights / L2: first 16 pairs
    double wxA[8], wxB[8];       // L1: x-part weights / L2: last 8 pairs
    float bi, bf, bg, bo;
    float c = 0.0f;
    int u, sel, kh;

    if (isL1) {
        u = tid >> 2; sel = (tid >> 1) & 1; kh = tid & 1;
        const int gA = sel ? (128 + u) : u;          // g : i
        const int gB = sel ? (192 + u) : (64 + u);   // o : f
        // pre-scale: gate A is sigmoid iff sel==0 (i); gate B always sigmoid
        const float scA = sel ? 1.0f : 0.5f;
        const float scB = 0.5f;
#pragma unroll
        for (int j = 0; j < 7; j++) {                // x pairs: p = 2j+kh < 13
            int p = 2 * j + kh;
            float a0 = 0.f, a1 = 0.f, q0 = 0.f, q1 = 0.f;
            if (p < 13) {
                int k0 = 2 * p, k1 = 2 * p + 1;
                a0 = scA * w_ih1[gA * 26 + k0]; a1 = scA * w_ih1[gA * 26 + k1];
                q0 = scB * w_ih1[gB * 26 + k0]; q1 = scB * w_ih1[gB * 26 + k1];
            }
            wxA[j] = pk2(a0, a1); wxB[j] = pk2(q0, q1);
        }
        wxA[7] = 0.0; wxB[7] = 0.0;
#pragma unroll
        for (int j = 0; j < 16; j++) {               // h pairs: p = 2j+kh < 32
            int p = 2 * j + kh;
            int k0 = 2 * p, k1 = 2 * p + 1;          // h index 0..63
            whA[j] = pk2(scA * w_hh1[gA * 64 + k0], scA * w_hh1[gA * 64 + k1]);
            whB[j] = pk2(scB * w_hh1[gB * 64 + k0], scB * w_hh1[gB * 64 + k1]);
        }
        bi = 0.5f * (b_ih1[u] + b_hh1[u]);
        bf = 0.5f * (b_ih1[64 + u] + b_hh1[64 + u]);
        bg =         b_ih1[128 + u] + b_hh1[128 + u];
        bo = 0.5f * (b_ih1[192 + u] + b_hh1[192 + u]);
    } else {
        const int t2 = tid - 256;
        u = t2 >> 2; sel = (t2 >> 1) & 1; kh = t2 & 1;
        const int gA = sel ? (64 + u) : u;
        const int gB = sel ? (96 + u) : (32 + u);
        const float scA = sel ? 1.0f : 0.5f;
        const float scB = 0.5f;
#pragma unroll
        for (int kk = 0; kk < 24; kk++) {
            int p = kh * 24 + kk;
            int k0 = 2 * p, k1 = 2 * p + 1;
            float a0 = scA * ((k0 < 64) ? w_ih2[gA * 64 + k0] : w_hh2[gA * 32 + k0 - 64]);
            float a1 = scA * ((k1 < 64) ? w_ih2[gA * 64 + k1] : w_hh2[gA * 32 + k1 - 64]);
            float q0 = scB * ((k0 < 64) ? w_ih2[gB * 64 + k0] : w_hh2[gB * 32 + k0 - 64]);
            float q1 = scB * ((k1 < 64) ? w_ih2[gB * 64 + k1] : w_hh2[gB * 32 + k1 - 64]);
            if (kk < 16) { whA[kk] = pk2(a0, a1); whB[kk] = pk2(q0, q1); }
            else         { wxA[kk - 16] = pk2(a0, a1); wxB[kk - 16] = pk2(q0, q1); }
        }
        bi = 0.5f * (b_ih2[u] + b_hh2[u]);
        bf = 0.5f * (b_ih2[32 + u] + b_hh2[32 + u]);
        bg =         b_ih2[64 + u] + b_hh2[64 + u];
        bo = 0.5f * (b_ih2[96 + u] + b_hh2[96 + u]);
    }

    const int hrow = u >> 1;
    const int hlane = u & 1;
    const int myb = 2 * kh + sel;

    // Zero buffers + init flags
    for (int idx = tid; idx < 2 * 32 * 8; idx += 384) ((float*)v1h)[idx] = 0.0f;
    for (int idx = tid; idx < 2 * 14 * 8; idx += 384) ((float*)xbuf)[idx] = 0.0f;
    for (int idx = tid; idx < 4 * 48 * 8; idx += 384) ((float*)v2s)[idx] = 0.0f;
    if (tid == 0) { flag1 = -1; flag2 = 0; }

    // x layout: x[b][i][t]  (loaders are L1 threads)
    const int xi = tid % 26;
    const int xb = tid / 26;
    const bool isldr = tid < 104;
    const int xrow = xi >> 1, xcol = xb * 2 + (xi & 1);
    const float* xptr = x + (size_t)(bbase + xb) * 26 * T_STEPS + (size_t)xi * T_STEPS;
    __syncthreads();
    if (isldr) {
        xbuf[0][xrow][xcol] = xptr[0];
        xbuf[1][xrow][xcol] = xptr[1];
    }
    __syncthreads();

    // carried x-part accumulators
    double xA0 = 0, xA1 = 0, xA2 = 0, xA3 = 0, xB0 = 0, xB1 = 0, xB2 = 0, xB3 = 0;
    if (isL1) {   // precompute x-part for step 0 from xbuf[0]
#pragma unroll
        for (int j = 0; j < 7; j++) {
            const float* r = &xbuf[0][2 * j + kh][0];
            double2 vlo = *(const double2*)r;
            double2 vhi = *(const double2*)(r + 4);
            fma2(xA0, wxA[j], vlo.x); fma2(xA1, wxA[j], vlo.y);
            fma2(xA2, wxA[j], vhi.x); fma2(xA3, wxA[j], vhi.y);
            fma2(xB0, wxB[j], vlo.x); fma2(xB1, wxB[j], vlo.y);
            fma2(xB2, wxB[j], vhi.x); fma2(xB3, wxB[j], vhi.y);
        }
    }

    // L1 body at iter n: reads v1h[cur] + carried xacc; writes v1h[nxt],
    // v2s[vb] rows 0..31 (vb = n&3); stages x[n+2]; precomputes xacc for n+1.
#define L1BODY(n, cur, nxt, vb)                                                    \
    {                                                                              \
        float xr = 0.0f;                                                           \
        const bool ldr = isldr && ((n) + 2 < T_STEPS);                             \
        if (ldr) xr = xptr[(n) + 2];                                               \
        double aA0 = xA0, aA1 = xA1, aA2 = xA2, aA3 = xA3;                         \
        double aB0 = xB0, aB1 = xB1, aB2 = xB2, aB3 = xB3;                         \
        _Pragma("unroll")                                                          \
        for (int j = 0; j < 16; j++) {                                             \
            const float* r = &v1h[cur][2 * j + kh][0];                             \
            double2 vlo = *(const double2*)r;                                      \
            double2 vhi = *(const double2*)(r + 4);                                \
            fma2(aA0, whA[j], vlo.x); fma2(aA1, whA[j], vlo.y);                    \
            fma2(aA2, whA[j], vhi.x); fma2(aA3, whA[j], vhi.y);                    \
            fma2(aB0, whB[j], vlo.x); fma2(aB1, whB[j], vlo.y);                    \
            fma2(aB2, whB[j], vhi.x); fma2(aB3, whB[j], vhi.y);                    \
        }                                                                          \
        float pA0 = fold(aA0), pA1 = fold(aA1), pA2 = fold(aA2), pA3 = fold(aA3);  \
        float pB0 = fold(aB0), pB1 = fold(aB1), pB2 = fold(aB2), pB3 = fold(aB3);  \
        float sA0 = kh ? pA0 : pA2, sA1 = kh ? pA1 : pA3;                          \
        float sB0 = kh ? pB0 : pB2, sB1 = kh ? pB1 : pB3;                          \
        sA0 = __shfl_xor_sync(0xffffffffu, sA0, 1);                                \
        sA1 = __shfl_xor_sync(0xffffffffu, sA1, 1);                                \
        sB0 = __shfl_xor_sync(0xffffffffu, sB0, 1);                                \
        sB1 = __shfl_xor_sync(0xffffffffu, sB1, 1);                                \
        float mA0 = (kh ? pA2 : pA0) + sA0;                                        \
        float mA1 = (kh ? pA3 : pA1) + sA1;                                        \
        float mB0 = (kh ? pB2 : pB0) + sB0;                                        \
        float mB1 = (kh ? pB3 : pB1) + sB1;                                        \
        float rA = __shfl_xor_sync(0xffffffffu, sel ? mA0 : mA1, 2);               \
        float rB = __shfl_xor_sync(0xffffffffu, sel ? mB0 : mB1, 2);               \
        float ownA = sel ? mA1 : mA0, ownB = sel ? mB1 : mB0;                      \
        float gi = (sel ? rA : ownA) + bi;                                         \
        float gf = (sel ? rB : ownB) + bf;                                         \
        float gg = (sel ? ownA : rA) + bg;                                         \
        float go = (sel ? ownB : rB) + bo;                                         \
        gi = sigf_h(gi); gf = sigf_h(gf); gg = tanh_fast(gg); go = sigf_h(go);     \
        c = fmaf(gf, c, gi * gg);                                                  \
        float h = go * tanh_fast(c);                                               \
        WAIT_GE(&flag2, (n) - 3);   /* ring slot vb free? (3-step slack) */        \
        v1h[nxt][hrow][myb * 2 + hlane] = h;                                       \
        v2s[vb][hrow][myb * 2 + hlane] = h;                                        \
        if (ldr) xbuf[cur][xrow][xcol] = xr;                                       \
        if ((n) + 1 < T_STEPS) {                                                   \
            xA0 = 0; xA1 = 0; xA2 = 0; xA3 = 0;                                    \
            xB0 = 0; xB1 = 0; xB2 = 0; xB3 = 0;                                    \
            _Pragma("unroll")                                                      \
            for (int j = 0; j < 7; j++) {                                          \
                const float* r = &xbuf[nxt][2 * j + kh][0];                        \
                double2 vlo = *(const double2*)r;                                  \
                double2 vhi = *(const double2*)(r + 4);                            \
                fma2(xA0, wxA[j], vlo.x); fma2(xA1, wxA[j], vlo.y);                \
                fma2(xA2, wxA[j], vhi.x); fma2(xA3, wxA[j], vhi.y);                \
                fma2(xB0, wxB[j], vlo.x); fma2(xB1, wxB[j], vlo.y);                \
                fma2(xB2, wxB[j], vhi.x); fma2(xB3, wxB[j], vhi.y);                \
            }                                                                      \
        }                                                                          \
        asm volatile("bar.sync 1, 256;" ::: "memory");                             \
        if (tid == 0) st_rel(&flag1, (n));                                         \
    }

    // L2 body at iter n (computes LSTM-2 step n-1): reads v2s[rd] (rd=(n-1)&3),
    // writes h2 into v2s[wr] rows 32..47 (wr=n&3).
#define L2BODY(n, rd, wr)                                                          \
    {                                                                              \
        WAIT_GE(&flag1, (n) - 1);   /* h1 of step n-1 published? */                \
        double aA0 = 0, aA1 = 0, aA2 = 0, aA3 = 0;                                 \
        double aB0 = 0, aB1 = 0, aB2 = 0, aB3 = 0;                                 \
        const float* base = &v2s[rd][kh * 24][0];                                  \
        _Pragma("unroll")                                                          \
        for (int kk = 0; kk < 24; kk++) {                                          \
            const float* r = base + 8 * kk;                                        \
            double2 vlo = *(const double2*)r;                                      \
            double2 vhi = *(const double2*)(r + 4);                                \
            double wa = (kk < 16) ? whA[kk] : wxA[kk - 16];                        \
            double wb = (kk < 16) ? whB[kk] : wxB[kk - 16];                        \
            fma2(aA0, wa, vlo.x); fma2(aA1, wa, vlo.y);                            \
            fma2(aA2, wa, vhi.x); fma2(aA3, wa, vhi.y);                            \
            fma2(aB0, wb, vlo.x); fma2(aB1, wb, vlo.y);                            \
            fma2(aB2, wb, vhi.x); fma2(aB3, wb, vhi.y);                            \
        }                                                                          \
        float pA0 = fold(aA0), pA1 = fold(aA1), pA2 = fold(aA2), pA3 = fold(aA3);  \
        float pB0 = fold(aB0), pB1 = fold(aB1), pB2 = fold(aB2), pB3 = fold(aB3);  \
        float sA0 = kh ? pA0 : pA2, sA1 = kh ? pA1 : pA3;                          \
        float sB0 = kh ? pB0 : pB2, sB1 = kh ? pB1 : pB3;                          \
        sA0 = __shfl_xor_sync(0xffffffffu, sA0, 1);                                \
        sA1 = __shfl_xor_sync(0xffffffffu, sA1, 1);                                \
        sB0 = __shfl_xor_sync(0xffffffffu, sB0, 1);                                \
        sB1 = __shfl_xor_sync(0xffffffffu, sB1, 1);                                \
        float mA0 = (kh ? pA2 : pA0) + sA0;                                        \
        float mA1 = (kh ? pA3 : pA1) + sA1;                                        \
        float mB0 = (kh ? pB2 : pB0) + sB0;                                        \
        float mB1 = (kh ? pB3 : pB1) + sB1;                                        \
        float rA = __shfl_xor_sync(0xffffffffu, sel ? mA0 : mA1, 2);               \
        float rB = __shfl_xor_sync(0xffffffffu, sel ? mB0 : mB1, 2);               \
        float ownA = sel ? mA1 : mA0, ownB = sel ? mB1 : mB0;                      \
        float gi = (sel ? rA : ownA) + bi;                                         \
        float gf = (sel ? rB : ownB) + bf;                                         \
        float gg = (sel ? ownA : rA) + bg;                                         \
        float go = (sel ? ownB : rB) + bo;                                         \
        gi = sigf_h(gi); gf = sigf_h(gf); gg = tanh_fast(gg); go = sigf_h(go);     \
        c = fmaf(gf, c, gi * gg);                                                  \
        float h = go * tanh_fast(c);                                               \
        v2s[wr][32 + hrow][myb * 2 + hlane] = h;                                   \
        asm volatile("bar.sync 2, 128;" ::: "memory");                             \
        if (tid == 256) st_rel(&flag2, (n));                                       \
    }

    if (isL1) {
        for (int n = 0; n < T_STEPS; n += 4) {
            L1BODY(n,     0, 1, 0);
            L1BODY(n + 1, 1, 0, 1);
            L1BODY(n + 2, 0, 1, 2);
            L1BODY(n + 3, 1, 0, 3);
        }
    } else {
        for (int n = 1; n <= T_STEPS; n += 4) {
            L2BODY(n,     0, 1);
            L2BODY(n + 1, 1, 2);
            L2BODY(n + 2, 2, 3);
            L2BODY(n + 3, 3, 0);
        }
    }
#undef L1BODY
#undef L2BODY
    __syncthreads();

    // ================= MLP head =================
    // final h2 (step 999, L2 iter 1000) is in v2s[0] pairs 32..47
    if (tid < 64) {
        const int b = tid >> 4, j = tid & 15;
        float s = b_fc1[j];
#pragma unroll
        for (int k2 = 0; k2 < 32; k2++)
            s = fmaf(v2s[0][32 + (k2 >> 1)][b * 2 + (k2 & 1)], w_fc1[j * 32 + k2], s);
        sf[b][j] = fmaxf(s, 0.0f);
    }
    __syncthreads();
    if (tid < 40) {
        const int b = tid / 10, o = tid % 10;
        float s = b_fc2[o];
#pragma unroll
        for (int j = 0; j < 16; j++) s = fmaf(sf[b][j], w_fc2[o * 16 + j], s);
        out[(bbase + b) * 10 + o] = s;
    }
}

extern "C" void kernel_launch(void* const* d_in, const int* in_sizes, int n_in,
                              void* d_out, int out_size)
{
    const float* x     = (const float*)d_in[0];
    const float* w_ih1 = (const float*)d_in[1];
    const float* w_hh1 = (const float*)d_in[2];
    const float* b_ih1 = (const float*)d_in[3];
    const float* b_hh1 = (const float*)d_in[4];
    const float* w_ih2 = (const float*)d_in[5];
    const float* w_hh2 = (const float*)d_in[6];
    const float* b_ih2 = (const float*)d_in[7];
    const float* b_hh2 = (const float*)d_in[8];
    const float* w_fc1 = (const float*)d_in[9];
    const float* b_fc1 = (const float*)d_in[10];
    const float* w_fc2 = (const float*)d_in[11];
    const float* b_fc2 = (const float*)d_in[12];
    float* out = (float*)d_out;

    audio_lstm_kernel<<<128, 384>>>(x, w_ih1, w_hh1, b_ih1, b_hh1,
                                    w_ih2, w_hh2, b_ih2, b_hh2,
                                    w_fc1, b_fc1, w_fc2, b_fc2, out);
}